// round 1
// baseline (speedup 1.0000x reference)
#include <cuda_runtime.h>
#include <cstdint>

// Problem constants
#define BB 4
#define CC 1024
#define CI 512
#define NN_TOK 2048   // T*H*W = 8*16*16

// Scratch (static device globals — no runtime allocation allowed)
__device__ float d_projg[BB * CI * NN_TOK];   // (b, ci, n) 16 MB
__device__ float d_projt[BB * CI * NN_TOK];   // 16 MB
__device__ float d_projp[BB * CI * NN_TOK];   // 16 MB
__device__ float d_attn [BB * NN_TOK * NN_TOK]; // (b, n, m) 64 MB
__device__ float d_y    [BB * CI * NN_TOK];   // (b, ci, n) 16 MB
__device__ float d_wy   [BB * CC * NN_TOK];   // (b, c, n) 32 MB

// ---------------------------------------------------------------------------
// Generic tiled SGEMM: C[m,n] = sum_k opA(A)[m,k] * opB(B)[k,n]  (+ bias[m])
// OPA: 0 -> A[m*lda + k]  (row-major M x K)
//      1 -> A[k*lda + m]  (row-major K x M, i.e. transposed access)
// OPB: 0 -> B[k*ldb + n]  (row-major K x N)
//      1 -> B[n*ldb + k]  (row-major N x K, i.e. transposed access)
// BM=BN=128, BK=16, 8x8 microtile, 256 threads. All dims must divide tiles.
// ---------------------------------------------------------------------------
#define BM 128
#define BNT 128
#define BK 16
#define TM 8
#define TN 8

template <int OPA, int OPB>
__global__ void __launch_bounds__(256)
gemm_kernel(const float* __restrict__ A, const float* __restrict__ B,
            float* __restrict__ C, const float* __restrict__ bias,
            int M, int N, int K, int lda, int ldb, int ldc,
            long strideA, long strideB, long strideC)
{
    __shared__ float As[BK][BM];
    __shared__ float Bs[BK][BNT];

    const int bz = blockIdx.z;
    A += (long)bz * strideA;
    B += (long)bz * strideB;
    C += (long)bz * strideC;

    const int bm = blockIdx.y * BM;
    const int bn = blockIdx.x * BNT;
    const int tid = threadIdx.x;

    float acc[TM][TN];
#pragma unroll
    for (int i = 0; i < TM; i++)
#pragma unroll
        for (int j = 0; j < TN; j++) acc[i][j] = 0.f;

    const int trow = (tid >> 4) * TM;   // 0..120
    const int tcol = (tid & 15) * TN;   // 0..120

    for (int k0 = 0; k0 < K; k0 += BK) {
        // ---- load A tile into As[k][m] ----
        if (OPA == 0) {
            // A[(bm+row)*lda + k0 + kk..kk+3] -> scatter to As
#pragma unroll
            for (int it = 0; it < 2; it++) {
                int idx = tid + it * 256;      // 0..511
                int row = idx >> 2;            // 0..127
                int kk  = (idx & 3) * 4;       // 0,4,8,12
                float4 v = *(const float4*)&A[(long)(bm + row) * lda + k0 + kk];
                As[kk + 0][row] = v.x;
                As[kk + 1][row] = v.y;
                As[kk + 2][row] = v.z;
                As[kk + 3][row] = v.w;
            }
        } else {
            // A[(k0+kk)*lda + bm + mm..mm+3] -> contiguous into As[kk][mm]
#pragma unroll
            for (int it = 0; it < 2; it++) {
                int idx = tid + it * 256;
                int kk = idx >> 5;             // 0..15
                int mm = (idx & 31) * 4;       // 0..124
                float4 v = *(const float4*)&A[(long)(k0 + kk) * lda + bm + mm];
                *(float4*)&As[kk][mm] = v;
            }
        }
        // ---- load B tile into Bs[k][n] ----
        if (OPB == 0) {
#pragma unroll
            for (int it = 0; it < 2; it++) {
                int idx = tid + it * 256;
                int kk = idx >> 5;
                int nn = (idx & 31) * 4;
                float4 v = *(const float4*)&B[(long)(k0 + kk) * ldb + bn + nn];
                *(float4*)&Bs[kk][nn] = v;
            }
        } else {
#pragma unroll
            for (int it = 0; it < 2; it++) {
                int idx = tid + it * 256;
                int col = idx >> 2;            // 0..127
                int kk  = (idx & 3) * 4;
                float4 v = *(const float4*)&B[(long)(bn + col) * ldb + k0 + kk];
                Bs[kk + 0][col] = v.x;
                Bs[kk + 1][col] = v.y;
                Bs[kk + 2][col] = v.z;
                Bs[kk + 3][col] = v.w;
            }
        }
        __syncthreads();

#pragma unroll
        for (int k = 0; k < BK; k++) {
            float ra[TM], rb[TN];
            *(float4*)&ra[0] = *(const float4*)&As[k][trow];
            *(float4*)&ra[4] = *(const float4*)&As[k][trow + 4];
            *(float4*)&rb[0] = *(const float4*)&Bs[k][tcol];
            *(float4*)&rb[4] = *(const float4*)&Bs[k][tcol + 4];
#pragma unroll
            for (int i = 0; i < TM; i++)
#pragma unroll
                for (int j = 0; j < TN; j++)
                    acc[i][j] += ra[i] * rb[j];
        }
        __syncthreads();
    }

#pragma unroll
    for (int i = 0; i < TM; i++) {
        float bv = bias ? bias[bm + trow + i] : 0.f;
#pragma unroll
        for (int j = 0; j < TN; j += 4) {
            float4 v;
            v.x = acc[i][j + 0] + bv;
            v.y = acc[i][j + 1] + bv;
            v.z = acc[i][j + 2] + bv;
            v.w = acc[i][j + 3] + bv;
            *(float4*)&C[(long)(bm + trow + i) * ldc + bn + tcol + j] = v;
        }
    }
}

// ---------------------------------------------------------------------------
// Row softmax over last dim (2048). One block (256 threads) per row; the whole
// row lives in registers: 1 read + 1 write of global memory.
// ---------------------------------------------------------------------------
__global__ void __launch_bounds__(256) softmax_kernel(float* __restrict__ f)
{
    float4* pv = (float4*)(f + (size_t)blockIdx.x * NN_TOK);
    const int tid = threadIdx.x;
    float4 a = pv[tid];
    float4 b = pv[tid + 256];

    float m = fmaxf(fmaxf(fmaxf(a.x, a.y), fmaxf(a.z, a.w)),
                    fmaxf(fmaxf(b.x, b.y), fmaxf(b.z, b.w)));
    __shared__ float red[8];
#pragma unroll
    for (int o = 16; o > 0; o >>= 1) m = fmaxf(m, __shfl_xor_sync(0xffffffffu, m, o));
    if ((tid & 31) == 0) red[tid >> 5] = m;
    __syncthreads();
    float mm = red[0];
#pragma unroll
    for (int i = 1; i < 8; i++) mm = fmaxf(mm, red[i]);
    __syncthreads();

    a.x = expf(a.x - mm); a.y = expf(a.y - mm); a.z = expf(a.z - mm); a.w = expf(a.w - mm);
    b.x = expf(b.x - mm); b.y = expf(b.y - mm); b.z = expf(b.z - mm); b.w = expf(b.w - mm);
    float s = (a.x + a.y) + (a.z + a.w) + (b.x + b.y) + (b.z + b.w);
#pragma unroll
    for (int o = 16; o > 0; o >>= 1) s += __shfl_xor_sync(0xffffffffu, s, o);
    if ((tid & 31) == 0) red[tid >> 5] = s;
    __syncthreads();
    float ssum = 0.f;
#pragma unroll
    for (int i = 0; i < 8; i++) ssum += red[i];

    float inv = 1.0f / ssum;
    a.x *= inv; a.y *= inv; a.z *= inv; a.w *= inv;
    b.x *= inv; b.y *= inv; b.z *= inv; b.w *= inv;
    pv[tid] = a;
    pv[tid + 256] = b;
}

// ---------------------------------------------------------------------------
// BatchNorm (training: mean/var over batch+spatial per channel) + affine +
// residual. One block per channel c; values (4*2048 = 8192) are held in
// registers (32/thread) between the stats pass and the normalize pass.
// ---------------------------------------------------------------------------
__global__ void __launch_bounds__(256)
bn_residual_kernel(const float* __restrict__ wy, const float* __restrict__ x,
                   const float* __restrict__ gamma, const float* __restrict__ beta,
                   float* __restrict__ out)
{
    const int c = blockIdx.x;
    const int tid = threadIdx.x;

    float vals[32];
    float s = 0.f, ss = 0.f;
#pragma unroll
    for (int b = 0; b < BB; b++) {
        const float* p = wy + ((size_t)b * CC + c) * NN_TOK;
#pragma unroll
        for (int j = 0; j < 8; j++) {
            float v = p[tid + j * 256];
            vals[b * 8 + j] = v;
            s += v;
            ss += v * v;
        }
    }
    __shared__ float r1[8], r2[8];
#pragma unroll
    for (int o = 16; o > 0; o >>= 1) {
        s  += __shfl_xor_sync(0xffffffffu, s, o);
        ss += __shfl_xor_sync(0xffffffffu, ss, o);
    }
    if ((tid & 31) == 0) { r1[tid >> 5] = s; r2[tid >> 5] = ss; }
    __syncthreads();
    s = 0.f; ss = 0.f;
#pragma unroll
    for (int i = 0; i < 8; i++) { s += r1[i]; ss += r2[i]; }

    const float cnt = (float)(BB * NN_TOK);
    float mean = s / cnt;
    float var = ss / cnt - mean * mean;
    float scale = rsqrtf(var + 1e-5f) * gamma[c];
    float shift = beta[c] - mean * scale;

#pragma unroll
    for (int b = 0; b < BB; b++) {
        size_t off = ((size_t)b * CC + c) * NN_TOK;
#pragma unroll
        for (int j = 0; j < 8; j++) {
            int n = tid + j * 256;
            out[off + n] = vals[b * 8 + j] * scale + shift + x[off + n];
        }
    }
}

// ---------------------------------------------------------------------------
extern "C" void kernel_launch(void* const* d_in, const int* in_sizes, int n_in,
                              void* d_out, int out_size)
{
    const float* x       = (const float*)d_in[0];
    const float* g_w     = (const float*)d_in[1];
    const float* g_b     = (const float*)d_in[2];
    const float* theta_w = (const float*)d_in[3];
    const float* theta_b = (const float*)d_in[4];
    const float* phi_w   = (const float*)d_in[5];
    const float* phi_b   = (const float*)d_in[6];
    const float* w_w     = (const float*)d_in[7];
    const float* w_b     = (const float*)d_in[8];
    const float* bn_g    = (const float*)d_in[9];
    const float* bn_b    = (const float*)d_in[10];
    float* out = (float*)d_out;

    float *pg, *pt, *pp, *attn, *y, *wy;
    cudaGetSymbolAddress((void**)&pg,   d_projg);
    cudaGetSymbolAddress((void**)&pt,   d_projt);
    cudaGetSymbolAddress((void**)&pp,   d_projp);
    cudaGetSymbolAddress((void**)&attn, d_attn);
    cudaGetSymbolAddress((void**)&y,    d_y);
    cudaGetSymbolAddress((void**)&wy,   d_wy);

    const long sX  = (long)CC * NN_TOK;     // x batch stride
    const long sP  = (long)CI * NN_TOK;     // projection batch stride
    const long sA  = (long)NN_TOK * NN_TOK; // attn batch stride
    const long sW  = (long)CC * NN_TOK;     // w_y batch stride

    dim3 blk(256);

    // Projections: P[b, o, n] = sum_c W[o,c] * x[b,c,n]  (M=512, N=2048, K=1024)
    dim3 gProj(NN_TOK / BNT, CI / BM, BB);
    gemm_kernel<0, 0><<<gProj, blk>>>(g_w,     x, pg, g_b,     CI, NN_TOK, CC, CC, NN_TOK, NN_TOK, 0, sX, sP);
    gemm_kernel<0, 0><<<gProj, blk>>>(theta_w, x, pt, theta_b, CI, NN_TOK, CC, CC, NN_TOK, NN_TOK, 0, sX, sP);
    gemm_kernel<0, 0><<<gProj, blk>>>(phi_w,   x, pp, phi_b,   CI, NN_TOK, CC, CC, NN_TOK, NN_TOK, 0, sX, sP);

    // f[b, n, m] = sum_i theta[b,i,n] * phi[b,i,m]  (TN: M=N=2048, K=512)
    dim3 gF(NN_TOK / BNT, NN_TOK / BM, BB);
    gemm_kernel<1, 0><<<gF, blk>>>(pt, pp, attn, nullptr,
                                   NN_TOK, NN_TOK, CI, NN_TOK, NN_TOK, NN_TOK, sP, sP, sA);

    // softmax over last dim
    softmax_kernel<<<BB * NN_TOK, 256>>>(attn);

    // y[b, o, n] = sum_m g[b,o,m] * attn[b,n,m]  (NT: M=512, N=2048, K=2048)
    dim3 gY(NN_TOK / BNT, CI / BM, BB);
    gemm_kernel<0, 1><<<gY, blk>>>(pg, attn, y, nullptr,
                                   CI, NN_TOK, NN_TOK, NN_TOK, NN_TOK, NN_TOK, sP, sA, sP);

    // w_y[b, c, n] = sum_o w_w[c,o] * y[b,o,n] + w_b[c]  (M=1024, N=2048, K=512)
    dim3 gW(NN_TOK / BNT, CC / BM, BB);
    gemm_kernel<0, 0><<<gW, blk>>>(w_w, y, wy, w_b,
                                   CC, NN_TOK, CI, CI, NN_TOK, NN_TOK, 0, sP, sW);

    // BN (over batch+spatial per channel) + affine + residual
    bn_residual_kernel<<<CC, 256>>>(wy, x, bn_g, bn_b, out);
}

// round 2
// speedup vs baseline: 1.0042x; 1.0042x over previous
#include <cuda_runtime.h>
#include <cstdint>

// Problem constants
#define BB 4
#define CC 1024
#define CI 512
#define NN_TOK 2048   // T*H*W = 8*16*16

// Scratch (static device globals — no runtime allocation allowed)
__device__ float d_projg[BB * CI * NN_TOK];   // (b, ci, n) 16 MB
__device__ float d_projt[BB * CI * NN_TOK];   // 16 MB
__device__ float d_projp[BB * CI * NN_TOK];   // 16 MB
__device__ float d_attn [BB * NN_TOK * NN_TOK]; // (b, n, m) 64 MB
__device__ float d_y    [BB * CI * NN_TOK];   // (b, ci, n) 16 MB
__device__ float d_wy   [BB * CC * NN_TOK];   // (b, c, n) 32 MB

// ---------------------------------------------------------------------------
// Generic tiled SGEMM: C[m,n] = sum_k opA(A)[m,k] * opB(B)[k,n]  (+ bias[m])
// OPA: 0 -> A[m*lda + k]  (row-major M x K)
//      1 -> A[k*lda + m]  (row-major K x M, i.e. transposed access)
// OPB: 0 -> B[k*ldb + n]  (row-major K x N)
//      1 -> B[n*ldb + k]  (row-major N x K, i.e. transposed access)
// BM=BN=128, BK=16, 8x8 microtile, 256 threads. All dims must divide tiles.
// ---------------------------------------------------------------------------
#define BM 128
#define BNT 128
#define BK 16
#define TM 8
#define TN 8

template <int OPA, int OPB>
__global__ void __launch_bounds__(256)
gemm_kernel(const float* __restrict__ A, const float* __restrict__ B,
            float* __restrict__ C, const float* __restrict__ bias,
            int M, int N, int K, int lda, int ldb, int ldc,
            long strideA, long strideB, long strideC)
{
    __shared__ float As[BK][BM];
    __shared__ float Bs[BK][BNT];

    const int bz = blockIdx.z;
    A += (long)bz * strideA;
    B += (long)bz * strideB;
    C += (long)bz * strideC;

    const int bm = blockIdx.y * BM;
    const int bn = blockIdx.x * BNT;
    const int tid = threadIdx.x;

    float acc[TM][TN];
#pragma unroll
    for (int i = 0; i < TM; i++)
#pragma unroll
        for (int j = 0; j < TN; j++) acc[i][j] = 0.f;

    const int trow = (tid >> 4) * TM;   // 0..120
    const int tcol = (tid & 15) * TN;   // 0..120

    for (int k0 = 0; k0 < K; k0 += BK) {
        // ---- load A tile into As[k][m] ----
        if (OPA == 0) {
            // A[(bm+row)*lda + k0 + kk..kk+3] -> scatter to As
#pragma unroll
            for (int it = 0; it < 2; it++) {
                int idx = tid + it * 256;      // 0..511
                int row = idx >> 2;            // 0..127
                int kk  = (idx & 3) * 4;       // 0,4,8,12
                float4 v = *(const float4*)&A[(long)(bm + row) * lda + k0 + kk];
                As[kk + 0][row] = v.x;
                As[kk + 1][row] = v.y;
                As[kk + 2][row] = v.z;
                As[kk + 3][row] = v.w;
            }
        } else {
            // A[(k0+kk)*lda + bm + mm..mm+3] -> contiguous into As[kk][mm]
#pragma unroll
            for (int it = 0; it < 2; it++) {
                int idx = tid + it * 256;
                int kk = idx >> 5;             // 0..15
                int mm = (idx & 31) * 4;       // 0..124
                float4 v = *(const float4*)&A[(long)(k0 + kk) * lda + bm + mm];
                *(float4*)&As[kk][mm] = v;
            }
        }
        // ---- load B tile into Bs[k][n] ----
        if (OPB == 0) {
#pragma unroll
            for (int it = 0; it < 2; it++) {
                int idx = tid + it * 256;
                int kk = idx >> 5;
                int nn = (idx & 31) * 4;
                float4 v = *(const float4*)&B[(long)(k0 + kk) * ldb + bn + nn];
                *(float4*)&Bs[kk][nn] = v;
            }
        } else {
#pragma unroll
            for (int it = 0; it < 2; it++) {
                int idx = tid + it * 256;
                int col = idx >> 2;            // 0..127
                int kk  = (idx & 3) * 4;
                float4 v = *(const float4*)&B[(long)(bn + col) * ldb + k0 + kk];
                Bs[kk + 0][col] = v.x;
                Bs[kk + 1][col] = v.y;
                Bs[kk + 2][col] = v.z;
                Bs[kk + 3][col] = v.w;
            }
        }
        __syncthreads();

#pragma unroll
        for (int k = 0; k < BK; k++) {
            float ra[TM], rb[TN];
            *(float4*)&ra[0] = *(const float4*)&As[k][trow];
            *(float4*)&ra[4] = *(const float4*)&As[k][trow + 4];
            *(float4*)&rb[0] = *(const float4*)&Bs[k][tcol];
            *(float4*)&rb[4] = *(const float4*)&Bs[k][tcol + 4];
#pragma unroll
            for (int i = 0; i < TM; i++)
#pragma unroll
                for (int j = 0; j < TN; j++)
                    acc[i][j] += ra[i] * rb[j];
        }
        __syncthreads();
    }

#pragma unroll
    for (int i = 0; i < TM; i++) {
        float bv = bias ? bias[bm + trow + i] : 0.f;
#pragma unroll
        for (int j = 0; j < TN; j += 4) {
            float4 v;
            v.x = acc[i][j + 0] + bv;
            v.y = acc[i][j + 1] + bv;
            v.z = acc[i][j + 2] + bv;
            v.w = acc[i][j + 3] + bv;
            *(float4*)&C[(long)(bm + trow + i) * ldc + bn + tcol + j] = v;
        }
    }
}

// ---------------------------------------------------------------------------
// Row softmax over last dim (2048). One block (256 threads) per row; the whole
// row lives in registers: 1 read + 1 write of global memory.
// ---------------------------------------------------------------------------
__global__ void __launch_bounds__(256) softmax_kernel(float* __restrict__ f)
{
    float4* pv = (float4*)(f + (size_t)blockIdx.x * NN_TOK);
    const int tid = threadIdx.x;
    float4 a = pv[tid];
    float4 b = pv[tid + 256];

    float m = fmaxf(fmaxf(fmaxf(a.x, a.y), fmaxf(a.z, a.w)),
                    fmaxf(fmaxf(b.x, b.y), fmaxf(b.z, b.w)));
    __shared__ float red[8];
#pragma unroll
    for (int o = 16; o > 0; o >>= 1) m = fmaxf(m, __shfl_xor_sync(0xffffffffu, m, o));
    if ((tid & 31) == 0) red[tid >> 5] = m;
    __syncthreads();
    float mm = red[0];
#pragma unroll
    for (int i = 1; i < 8; i++) mm = fmaxf(mm, red[i]);
    __syncthreads();

    a.x = expf(a.x - mm); a.y = expf(a.y - mm); a.z = expf(a.z - mm); a.w = expf(a.w - mm);
    b.x = expf(b.x - mm); b.y = expf(b.y - mm); b.z = expf(b.z - mm); b.w = expf(b.w - mm);
    float s = (a.x + a.y) + (a.z + a.w) + (b.x + b.y) + (b.z + b.w);
#pragma unroll
    for (int o = 16; o > 0; o >>= 1) s += __shfl_xor_sync(0xffffffffu, s, o);
    if ((tid & 31) == 0) red[tid >> 5] = s;
    __syncthreads();
    float ssum = 0.f;
#pragma unroll
    for (int i = 0; i < 8; i++) ssum += red[i];

    float inv = 1.0f / ssum;
    a.x *= inv; a.y *= inv; a.z *= inv; a.w *= inv;
    b.x *= inv; b.y *= inv; b.z *= inv; b.w *= inv;
    pv[tid] = a;
    pv[tid + 256] = b;
}

// ---------------------------------------------------------------------------
// BatchNorm (training: mean/var over batch+spatial per channel) + affine +
// residual. One block per channel c; values (4*2048 = 8192) are held in
// registers (32/thread) between the stats pass and the normalize pass.
// ---------------------------------------------------------------------------
__global__ void __launch_bounds__(256)
bn_residual_kernel(const float* __restrict__ wy, const float* __restrict__ x,
                   const float* __restrict__ gamma, const float* __restrict__ beta,
                   float* __restrict__ out)
{
    const int c = blockIdx.x;
    const int tid = threadIdx.x;

    float vals[32];
    float s = 0.f, ss = 0.f;
#pragma unroll
    for (int b = 0; b < BB; b++) {
        const float* p = wy + ((size_t)b * CC + c) * NN_TOK;
#pragma unroll
        for (int j = 0; j < 8; j++) {
            float v = p[tid + j * 256];
            vals[b * 8 + j] = v;
            s += v;
            ss += v * v;
        }
    }
    __shared__ float r1[8], r2[8];
#pragma unroll
    for (int o = 16; o > 0; o >>= 1) {
        s  += __shfl_xor_sync(0xffffffffu, s, o);
        ss += __shfl_xor_sync(0xffffffffu, ss, o);
    }
    if ((tid & 31) == 0) { r1[tid >> 5] = s; r2[tid >> 5] = ss; }
    __syncthreads();
    s = 0.f; ss = 0.f;
#pragma unroll
    for (int i = 0; i < 8; i++) { s += r1[i]; ss += r2[i]; }

    const float cnt = (float)(BB * NN_TOK);
    float mean = s / cnt;
    float var = ss / cnt - mean * mean;
    float scale = rsqrtf(var + 1e-5f) * gamma[c];
    float shift = beta[c] - mean * scale;

#pragma unroll
    for (int b = 0; b < BB; b++) {
        size_t off = ((size_t)b * CC + c) * NN_TOK;
#pragma unroll
        for (int j = 0; j < 8; j++) {
            int n = tid + j * 256;
            out[off + n] = vals[b * 8 + j] * scale + shift + x[off + n];
        }
    }
}

// ---------------------------------------------------------------------------
extern "C" void kernel_launch(void* const* d_in, const int* in_sizes, int n_in,
                              void* d_out, int out_size)
{
    const float* x       = (const float*)d_in[0];
    const float* g_w     = (const float*)d_in[1];
    const float* g_b     = (const float*)d_in[2];
    const float* theta_w = (const float*)d_in[3];
    const float* theta_b = (const float*)d_in[4];
    const float* phi_w   = (const float*)d_in[5];
    const float* phi_b   = (const float*)d_in[6];
    const float* w_w     = (const float*)d_in[7];
    const float* w_b     = (const float*)d_in[8];
    const float* bn_g    = (const float*)d_in[9];
    const float* bn_b    = (const float*)d_in[10];
    float* out = (float*)d_out;

    float *pg, *pt, *pp, *attn, *y, *wy;
    cudaGetSymbolAddress((void**)&pg,   d_projg);
    cudaGetSymbolAddress((void**)&pt,   d_projt);
    cudaGetSymbolAddress((void**)&pp,   d_projp);
    cudaGetSymbolAddress((void**)&attn, d_attn);
    cudaGetSymbolAddress((void**)&y,    d_y);
    cudaGetSymbolAddress((void**)&wy,   d_wy);

    const long sX  = (long)CC * NN_TOK;     // x batch stride
    const long sP  = (long)CI * NN_TOK;     // projection batch stride
    const long sA  = (long)NN_TOK * NN_TOK; // attn batch stride
    const long sW  = (long)CC * NN_TOK;     // w_y batch stride

    dim3 blk(256);

    // Projections: P[b, o, n] = sum_c W[o,c] * x[b,c,n]  (M=512, N=2048, K=1024)
    dim3 gProj(NN_TOK / BNT, CI / BM, BB);
    gemm_kernel<0, 0><<<gProj, blk>>>(g_w,     x, pg, g_b,     CI, NN_TOK, CC, CC, NN_TOK, NN_TOK, 0, sX, sP);
    gemm_kernel<0, 0><<<gProj, blk>>>(theta_w, x, pt, theta_b, CI, NN_TOK, CC, CC, NN_TOK, NN_TOK, 0, sX, sP);
    gemm_kernel<0, 0><<<gProj, blk>>>(phi_w,   x, pp, phi_b,   CI, NN_TOK, CC, CC, NN_TOK, NN_TOK, 0, sX, sP);

    // f[b, n, m] = sum_i theta[b,i,n] * phi[b,i,m]  (TN: M=N=2048, K=512)
    dim3 gF(NN_TOK / BNT, NN_TOK / BM, BB);
    gemm_kernel<1, 0><<<gF, blk>>>(pt, pp, attn, nullptr,
                                   NN_TOK, NN_TOK, CI, NN_TOK, NN_TOK, NN_TOK, sP, sP, sA);

    // softmax over last dim
    softmax_kernel<<<BB * NN_TOK, 256>>>(attn);

    // y[b, o, n] = sum_m g[b,o,m] * attn[b,n,m]  (NT: M=512, N=2048, K=2048)
    dim3 gY(NN_TOK / BNT, CI / BM, BB);
    gemm_kernel<0, 1><<<gY, blk>>>(pg, attn, y, nullptr,
                                   CI, NN_TOK, NN_TOK, NN_TOK, NN_TOK, NN_TOK, sP, sA, sP);

    // w_y[b, c, n] = sum_o w_w[c,o] * y[b,o,n] + w_b[c]  (M=1024, N=2048, K=512)
    dim3 gW(NN_TOK / BNT, CC / BM, BB);
    gemm_kernel<0, 0><<<gW, blk>>>(w_w, y, wy, w_b,
                                   CC, NN_TOK, CI, CI, NN_TOK, NN_TOK, 0, sP, sW);

    // BN (over batch+spatial per channel) + affine + residual
    bn_residual_kernel<<<CC, 256>>>(wy, x, bn_g, bn_b, out);
}

// round 4
// speedup vs baseline: 2.5286x; 2.5180x over previous
#include <cuda_runtime.h>
#include <cuda_bf16.h>
#include <cstdint>

typedef __nv_bfloat16 bf16;

#define BB 4
#define CC 1024
#define CIN 512
#define NT 2048

// ---------------- static scratch ----------------
__device__ __align__(256) bf16 s_xT_h[BB * NT * CC];
__device__ __align__(256) bf16 s_xT_l[BB * NT * CC];
__device__ __align__(256) bf16 s_wg_h[CIN * CC], s_wg_l[CIN * CC];
__device__ __align__(256) bf16 s_wt_h[CIN * CC], s_wt_l[CIN * CC];
__device__ __align__(256) bf16 s_wp_h[CIN * CC], s_wp_l[CIN * CC];
__device__ __align__(256) bf16 s_ww_h[CC * CIN], s_ww_l[CC * CIN];
__device__ __align__(256) bf16 s_th_h[BB * NT * CIN], s_th_l[BB * NT * CIN];
__device__ __align__(256) bf16 s_ph_h[BB * NT * CIN], s_ph_l[BB * NT * CIN];
__device__ __align__(256) bf16 s_gs_h[BB * CIN * NT], s_gs_l[BB * CIN * NT];
__device__ __align__(256) float s_f[BB * NT * NT];
__device__ __align__(256) bf16 s_at_h[BB * NT * NT], s_at_l[BB * NT * NT];
__device__ __align__(256) bf16 s_y_h[BB * NT * CIN], s_y_l[BB * NT * CIN];
__device__ __align__(256) float s_wy[BB * CC * NT];

// ---------------- helpers ----------------
__device__ __forceinline__ uint32_t smem_u32(const void* p) {
    uint32_t a;
    asm("{ .reg .u64 t; cvta.to.shared.u64 t, %1; cvt.u32.u64 %0, t; }" : "=r"(a) : "l"(p));
    return a;
}
__device__ __forceinline__ void st_split2(bf16* hi, bf16* lo, float v0, float v1) {
    bf16 h0 = __float2bfloat16(v0), h1 = __float2bfloat16(v1);
    *(uint32_t*)hi = (uint32_t)__bfloat16_as_ushort(h0) |
                     ((uint32_t)__bfloat16_as_ushort(h1) << 16);
    bf16 l0 = __float2bfloat16(v0 - __bfloat162float(h0));
    bf16 l1 = __float2bfloat16(v1 - __bfloat162float(h1));
    *(uint32_t*)lo = (uint32_t)__bfloat16_as_ushort(l0) |
                     ((uint32_t)__bfloat16_as_ushort(l1) << 16);
}
__device__ __forceinline__ void st_split4(bf16* hi, bf16* lo, float v0, float v1, float v2, float v3) {
    st_split2(hi, lo, v0, v1);
    st_split2(hi + 2, lo + 2, v2, v3);
}

// ---------------- HMMA GEMM ----------------
// D[r,c] = sum_k (Ah+Al)[r,k] * (Bh+Bl)[c,k]   via HH + HL + LH
// CTA tile 128x128, K-chunk 32, 8 warps (2x4), warp tile 64x32, 3-stage cp.async.
#define NSTG 3
#define STG_BYTES 32768          // Ah/Al/Bh/Bl each 128x32 bf16 = 8 KB
#define SMEM_TOTAL (NSTG * STG_BYTES)

// swizzled byte offset of 16B vector (row, kv) in a 128x32 bf16 tile
__device__ __forceinline__ uint32_t sw_off(int row, int kv) {
    return (uint32_t)(row * 64 + ((kv ^ ((row >> 1) & 3)) << 4));
}

__device__ __forceinline__ void cpa_tile(uint32_t sdst, const bf16* __restrict__ g,
                                         int ld, int k0, int tid) {
    int kv = tid & 3, r = tid >> 2;  // r in [0,64)
#pragma unroll
    for (int h = 0; h < 2; h++) {
        int row = r + h * 64;
        uint32_t dst = sdst + sw_off(row, kv);
        const void* src = g + (long)row * ld + k0 + kv * 8;
        asm volatile("cp.async.cg.shared.global [%0], [%1], 16;" :: "r"(dst), "l"(src));
    }
}

__device__ __forceinline__ void ldmA(uint32_t* r, uint32_t base, int m0, int k16, int lane) {
    int m = m0 + (lane & 15);
    int kv = k16 * 2 + (lane >> 4);
    uint32_t addr = base + sw_off(m, kv);
    asm volatile("ldmatrix.sync.aligned.m8n8.x4.shared.b16 {%0,%1,%2,%3}, [%4];"
                 : "=r"(r[0]), "=r"(r[1]), "=r"(r[2]), "=r"(r[3]) : "r"(addr));
}
// loads B frags for two adjacent n8-tiles: r[0],r[1] = tile n0..n0+7; r[2],r[3] = n0+8..15
__device__ __forceinline__ void ldmB(uint32_t* r, uint32_t base, int n0, int k16, int lane) {
    int row = n0 + (lane & 7) + ((lane >> 4) << 3);
    int kv = k16 * 2 + ((lane >> 3) & 1);
    uint32_t addr = base + sw_off(row, kv);
    asm volatile("ldmatrix.sync.aligned.m8n8.x4.shared.b16 {%0,%1,%2,%3}, [%4];"
                 : "=r"(r[0]), "=r"(r[1]), "=r"(r[2]), "=r"(r[3]) : "r"(addr));
}
__device__ __forceinline__ void mmaOp(float* c, const uint32_t* a, const uint32_t* b) {
    asm volatile(
        "mma.sync.aligned.m16n8k16.row.col.f32.bf16.bf16.f32 "
        "{%0,%1,%2,%3},{%4,%5,%6,%7},{%8,%9},{%0,%1,%2,%3};"
        : "+f"(c[0]), "+f"(c[1]), "+f"(c[2]), "+f"(c[3])
        : "r"(a[0]), "r"(a[1]), "r"(a[2]), "r"(a[3]), "r"(b[0]), "r"(b[1]));
}

template <int OUT_SPLIT>
__global__ void __launch_bounds__(256, 1)
gemm_tc(const bf16* __restrict__ aH, const bf16* __restrict__ aL, long aS, int lda,
        const bf16* __restrict__ bH, const bf16* __restrict__ bL, long bS, int ldb,
        float* __restrict__ outF, bf16* __restrict__ oH, bf16* __restrict__ oL,
        long oS, int ldc, const float* __restrict__ rBias,
        const float* __restrict__ cBias, int K)
{
    extern __shared__ char smraw[];
    const uint32_t sb = smem_u32(smraw);

    const int tid = threadIdx.x, wid = tid >> 5, lane = tid & 31;
    const int bn = blockIdx.x * 128, bm = blockIdx.y * 128, bz = blockIdx.z;
    const int wm = (wid >> 2) * 64;   // warp m offset (0,64)
    const int wn = (wid & 3) * 32;    // warp n offset (0..96)

    const bf16* A0 = aH + (long)bz * aS + (long)bm * lda;
    const bf16* A1 = aL + (long)bz * aS + (long)bm * lda;
    const bf16* B0 = bH + (long)bz * bS + (long)bn * ldb;
    const bf16* B1 = bL + (long)bz * bS + (long)bn * ldb;
    const int nch = K >> 5;

    float acc[4][4][4];
#pragma unroll
    for (int i = 0; i < 4; i++)
#pragma unroll
        for (int j = 0; j < 4; j++)
#pragma unroll
            for (int e = 0; e < 4; e++) acc[i][j][e] = 0.f;

    // prologue: stages 0, 1
#pragma unroll
    for (int s = 0; s < NSTG - 1; s++) {
        uint32_t st = sb + s * STG_BYTES;
        int k0 = s << 5;
        cpa_tile(st,         A0, lda, k0, tid);
        cpa_tile(st + 8192,  A1, lda, k0, tid);
        cpa_tile(st + 16384, B0, ldb, k0, tid);
        cpa_tile(st + 24576, B1, ldb, k0, tid);
        asm volatile("cp.async.commit_group;");
    }

    for (int c = 0; c < nch; c++) {
        asm volatile("cp.async.wait_group 1;");
        __syncthreads();
        // prefetch stage c + NSTG - 1
        if (c + NSTG - 1 < nch) {
            uint32_t st = sb + ((c + NSTG - 1) % NSTG) * STG_BYTES;
            int k0 = (c + NSTG - 1) << 5;
            cpa_tile(st,         A0, lda, k0, tid);
            cpa_tile(st + 8192,  A1, lda, k0, tid);
            cpa_tile(st + 16384, B0, ldb, k0, tid);
            cpa_tile(st + 24576, B1, ldb, k0, tid);
        }
        asm volatile("cp.async.commit_group;");

        const uint32_t st = sb + (c % NSTG) * STG_BYTES;
#pragma unroll
        for (int k16 = 0; k16 < 2; k16++) {
            uint32_t fAh[4][4], fAl[4][4], fBh[2][4], fBl[2][4];
#pragma unroll
            for (int mt = 0; mt < 4; mt++) {
                ldmA(fAh[mt], st,        wm + mt * 16, k16, lane);
                ldmA(fAl[mt], st + 8192, wm + mt * 16, k16, lane);
            }
            ldmB(fBh[0], st + 16384, wn,      k16, lane);
            ldmB(fBh[1], st + 16384, wn + 16, k16, lane);
            ldmB(fBl[0], st + 24576, wn,      k16, lane);
            ldmB(fBl[1], st + 24576, wn + 16, k16, lane);
#pragma unroll
            for (int mt = 0; mt < 4; mt++) {
#pragma unroll
                for (int nt = 0; nt < 4; nt++) {
                    const uint32_t* bh = &fBh[nt >> 1][(nt & 1) * 2];
                    const uint32_t* bl = &fBl[nt >> 1][(nt & 1) * 2];
                    mmaOp(acc[mt][nt], fAh[mt], bh);
                    mmaOp(acc[mt][nt], fAh[mt], bl);
                    mmaOp(acc[mt][nt], fAl[mt], bh);
                }
            }
        }
        __syncthreads();
    }

    // epilogue
    const int rr = lane >> 2;           // 0..7
    const int cc2 = (lane & 3) * 2;     // 0,2,4,6
#pragma unroll
    for (int mt = 0; mt < 4; mt++) {
#pragma unroll
        for (int nt = 0; nt < 4; nt++) {
            int row0 = bm + wm + mt * 16 + rr;
            int col = bn + wn + nt * 8 + cc2;
            float cb0 = cBias ? cBias[col] : 0.f;
            float cb1 = cBias ? cBias[col + 1] : 0.f;
#pragma unroll
            for (int h = 0; h < 2; h++) {
                int row = row0 + h * 8;
                float rb = rBias ? rBias[row] : 0.f;
                float v0 = acc[mt][nt][h * 2 + 0] + rb + cb0;
                float v1 = acc[mt][nt][h * 2 + 1] + rb + cb1;
                long o = (long)bz * oS + (long)row * ldc + col;
                if (OUT_SPLIT == 0) {
                    float2 w = make_float2(v0, v1);
                    *(float2*)(outF + o) = w;
                } else {
                    st_split2(oH + o, oL + o, v0, v1);
                }
            }
        }
    }
}

// ---------------- elementwise kernels ----------------
__global__ void __launch_bounds__(256) split_k(const float* __restrict__ w,
                                               bf16* __restrict__ hi, bf16* __restrict__ lo, int n)
{
    int i = blockIdx.x * 256 + threadIdx.x;
    if (i < n) {
        float v = w[i];
        bf16 h = __float2bfloat16(v);
        hi[i] = h;
        lo[i] = __float2bfloat16(v - __bfloat162float(h));
    }
}

__global__ void __launch_bounds__(256) xpose_split(const float* __restrict__ x,
                                                   bf16* __restrict__ hi, bf16* __restrict__ lo)
{
    __shared__ float t[32][33];
    const int b = blockIdx.z, n0 = blockIdx.x * 32, c0 = blockIdx.y * 32;
    const int tx = threadIdx.x & 31, ty = threadIdx.x >> 5;
#pragma unroll
    for (int i = 0; i < 4; i++) {
        int r = ty + i * 8;
        t[r][tx] = x[((long)b * CC + c0 + r) * NT + n0 + tx];
    }
    __syncthreads();
#pragma unroll
    for (int i = 0; i < 4; i++) {
        int r = ty + i * 8;
        float v = t[tx][r];
        long o = ((long)b * NT + n0 + r) * CC + c0 + tx;
        bf16 h = __float2bfloat16(v);
        hi[o] = h;
        lo[o] = __float2bfloat16(v - __bfloat162float(h));
    }
}

__global__ void __launch_bounds__(256) softmax_split(const float* __restrict__ f,
                                                     bf16* __restrict__ hi, bf16* __restrict__ lo)
{
    const float4* pv = (const float4*)(f + (size_t)blockIdx.x * NT);
    const int tid = threadIdx.x;
    float4 a = pv[tid], b = pv[tid + 256];
    float m = fmaxf(fmaxf(fmaxf(a.x, a.y), fmaxf(a.z, a.w)),
                    fmaxf(fmaxf(b.x, b.y), fmaxf(b.z, b.w)));
    __shared__ float red[8];
#pragma unroll
    for (int o = 16; o > 0; o >>= 1) m = fmaxf(m, __shfl_xor_sync(~0u, m, o));
    if ((tid & 31) == 0) red[tid >> 5] = m;
    __syncthreads();
    float mm = red[0];
#pragma unroll
    for (int i = 1; i < 8; i++) mm = fmaxf(mm, red[i]);
    __syncthreads();
    a.x = expf(a.x - mm); a.y = expf(a.y - mm); a.z = expf(a.z - mm); a.w = expf(a.w - mm);
    b.x = expf(b.x - mm); b.y = expf(b.y - mm); b.z = expf(b.z - mm); b.w = expf(b.w - mm);
    float s = (a.x + a.y) + (a.z + a.w) + (b.x + b.y) + (b.z + b.w);
#pragma unroll
    for (int o = 16; o > 0; o >>= 1) s += __shfl_xor_sync(~0u, s, o);
    if ((tid & 31) == 0) red[tid >> 5] = s;
    __syncthreads();
    float sum = 0.f;
#pragma unroll
    for (int i = 0; i < 8; i++) sum += red[i];
    float inv = 1.0f / sum;
    size_t off = (size_t)blockIdx.x * NT;
    st_split4(hi + off + tid * 4, lo + off + tid * 4,
              a.x * inv, a.y * inv, a.z * inv, a.w * inv);
    st_split4(hi + off + 1024 + tid * 4, lo + off + 1024 + tid * 4,
              b.x * inv, b.y * inv, b.z * inv, b.w * inv);
}

__global__ void __launch_bounds__(256)
bn_residual(const float* __restrict__ wy, const float* __restrict__ x,
            const float* __restrict__ gamma, const float* __restrict__ beta,
            float* __restrict__ out)
{
    const int c = blockIdx.x, tid = threadIdx.x;
    float vals[32], s = 0.f, ss = 0.f;
#pragma unroll
    for (int b = 0; b < BB; b++) {
        const float* p = wy + ((size_t)b * CC + c) * NT;
#pragma unroll
        for (int j = 0; j < 8; j++) {
            float v = p[tid + j * 256];
            vals[b * 8 + j] = v; s += v; ss += v * v;
        }
    }
    __shared__ float r1[8], r2[8];
#pragma unroll
    for (int o = 16; o > 0; o >>= 1) {
        s += __shfl_xor_sync(~0u, s, o);
        ss += __shfl_xor_sync(~0u, ss, o);
    }
    if ((tid & 31) == 0) { r1[tid >> 5] = s; r2[tid >> 5] = ss; }
    __syncthreads();
    s = 0.f; ss = 0.f;
#pragma unroll
    for (int i = 0; i < 8; i++) { s += r1[i]; ss += r2[i]; }
    const float cnt = (float)(BB * NT);
    float mean = s / cnt;
    float var = ss / cnt - mean * mean;
    float scale = rsqrtf(var + 1e-5f) * gamma[c];
    float shift = beta[c] - mean * scale;
#pragma unroll
    for (int b = 0; b < BB; b++) {
        size_t off = ((size_t)b * CC + c) * NT;
#pragma unroll
        for (int j = 0; j < 8; j++) {
            int n = tid + j * 256;
            out[off + n] = vals[b * 8 + j] * scale + shift + x[off + n];
        }
    }
}

// ---------------------------------------------------------------------------
extern "C" void kernel_launch(void* const* d_in, const int* in_sizes, int n_in,
                              void* d_out, int out_size)
{
    const float* x   = (const float*)d_in[0];
    const float* gw  = (const float*)d_in[1];
    const float* gb  = (const float*)d_in[2];
    const float* tw  = (const float*)d_in[3];
    const float* tb  = (const float*)d_in[4];
    const float* pw  = (const float*)d_in[5];
    const float* pb  = (const float*)d_in[6];
    const float* ww  = (const float*)d_in[7];
    const float* wb  = (const float*)d_in[8];
    const float* bg  = (const float*)d_in[9];
    const float* bbt = (const float*)d_in[10];
    float* out = (float*)d_out;

    bf16 *xTh, *xTl, *wgh, *wgl, *wth, *wtl, *wph, *wpl, *wwh, *wwl;
    bf16 *thh, *thl, *phh, *phl, *gsh, *gsl, *ath, *atl, *yh, *yl;
    float *ff, *wy;
    cudaGetSymbolAddress((void**)&xTh, s_xT_h); cudaGetSymbolAddress((void**)&xTl, s_xT_l);
    cudaGetSymbolAddress((void**)&wgh, s_wg_h); cudaGetSymbolAddress((void**)&wgl, s_wg_l);
    cudaGetSymbolAddress((void**)&wth, s_wt_h); cudaGetSymbolAddress((void**)&wtl, s_wt_l);
    cudaGetSymbolAddress((void**)&wph, s_wp_h); cudaGetSymbolAddress((void**)&wpl, s_wp_l);
    cudaGetSymbolAddress((void**)&wwh, s_ww_h); cudaGetSymbolAddress((void**)&wwl, s_ww_l);
    cudaGetSymbolAddress((void**)&thh, s_th_h); cudaGetSymbolAddress((void**)&thl, s_th_l);
    cudaGetSymbolAddress((void**)&phh, s_ph_h); cudaGetSymbolAddress((void**)&phl, s_ph_l);
    cudaGetSymbolAddress((void**)&gsh, s_gs_h); cudaGetSymbolAddress((void**)&gsl, s_gs_l);
    cudaGetSymbolAddress((void**)&ath, s_at_h); cudaGetSymbolAddress((void**)&atl, s_at_l);
    cudaGetSymbolAddress((void**)&yh,  s_y_h);  cudaGetSymbolAddress((void**)&yl,  s_y_l);
    cudaGetSymbolAddress((void**)&ff,  s_f);    cudaGetSymbolAddress((void**)&wy,  s_wy);

    cudaFuncSetAttribute(gemm_tc<0>, cudaFuncAttributeMaxDynamicSharedMemorySize, SMEM_TOTAL);
    cudaFuncSetAttribute(gemm_tc<1>, cudaFuncAttributeMaxDynamicSharedMemorySize, SMEM_TOTAL);

    split_k<<<(CIN * CC + 255) / 256, 256>>>(gw, wgh, wgl, CIN * CC);
    split_k<<<(CIN * CC + 255) / 256, 256>>>(tw, wth, wtl, CIN * CC);
    split_k<<<(CIN * CC + 255) / 256, 256>>>(pw, wph, wpl, CIN * CC);
    split_k<<<(CC * CIN + 255) / 256, 256>>>(ww, wwh, wwl, CC * CIN);
    xpose_split<<<dim3(NT / 32, CC / 32, BB), 256>>>(x, xTh, xTl);

    const long sXT = (long)NT * CC, sPR = (long)NT * CIN;
    const long sGS = (long)CIN * NT, sAT = (long)NT * NT, sWY = (long)CC * NT;

    // theta[b,n,o] (rows=NT, cols=CIN, K=CC)
    gemm_tc<1><<<dim3(CIN / 128, NT / 128, BB), 256, SMEM_TOTAL>>>(
        xTh, xTl, sXT, CC, wth, wtl, 0, CC, nullptr, thh, thl, sPR, CIN, nullptr, tb, CC);
    // phi[b,n,o]
    gemm_tc<1><<<dim3(CIN / 128, NT / 128, BB), 256, SMEM_TOTAL>>>(
        xTh, xTl, sXT, CC, wph, wpl, 0, CC, nullptr, phh, phl, sPR, CIN, nullptr, pb, CC);
    // g_s[b,o,m] (rows=CIN, cols=NT, K=CC)
    gemm_tc<1><<<dim3(NT / 128, CIN / 128, BB), 256, SMEM_TOTAL>>>(
        wgh, wgl, 0, CC, xTh, xTl, sXT, CC, nullptr, gsh, gsl, sGS, NT, gb, nullptr, CC);
    // f[b,n,m] (rows=NT, cols=NT, K=CIN)
    gemm_tc<0><<<dim3(NT / 128, NT / 128, BB), 256, SMEM_TOTAL>>>(
        thh, thl, sPR, CIN, phh, phl, sPR, CIN, ff, nullptr, nullptr, sAT, NT, nullptr, nullptr, CIN);
    // softmax -> split attn
    softmax_split<<<BB * NT, 256>>>(ff, ath, atl);
    // y[b,n,o] (rows=NT, cols=CIN, K=NT)
    gemm_tc<1><<<dim3(CIN / 128, NT / 128, BB), 256, SMEM_TOTAL>>>(
        ath, atl, sAT, NT, gsh, gsl, sGS, NT, nullptr, yh, yl, sPR, CIN, nullptr, nullptr, NT);
    // w_y[b,c,n] (rows=CC, cols=NT, K=CIN)
    gemm_tc<0><<<dim3(NT / 128, CC / 128, BB), 256, SMEM_TOTAL>>>(
        wwh, wwl, 0, CIN, yh, yl, sPR, CIN, wy, nullptr, nullptr, sWY, NT, wb, nullptr, CIN);
    // BN + residual
    bn_residual<<<CC, 256>>>(wy, x, bg, bbt, out);
}

// round 5
// speedup vs baseline: 2.8498x; 1.1270x over previous
#include <cuda_runtime.h>
#include <cuda_bf16.h>
#include <cstdint>

typedef __nv_bfloat16 bf16;

#define BB 4
#define CC 1024
#define CIN 512
#define NT 2048

// ---------------- static scratch ----------------
__device__ __align__(256) bf16 s_xT_h[BB * NT * CC];
__device__ __align__(256) bf16 s_xT_l[BB * NT * CC];
__device__ __align__(256) bf16 s_wg_h[CIN * CC], s_wg_l[CIN * CC];
__device__ __align__(256) bf16 s_wt_h[CIN * CC], s_wt_l[CIN * CC];
__device__ __align__(256) bf16 s_wp_h[CIN * CC], s_wp_l[CIN * CC];
__device__ __align__(256) bf16 s_ww_h[CC * CIN], s_ww_l[CC * CIN];
__device__ __align__(256) bf16 s_th_h[BB * NT * CIN], s_th_l[BB * NT * CIN];
__device__ __align__(256) bf16 s_ph_h[BB * NT * CIN], s_ph_l[BB * NT * CIN];
__device__ __align__(256) bf16 s_gs_h[BB * CIN * NT], s_gs_l[BB * CIN * NT];
__device__ __align__(256) float s_f[BB * NT * NT];
__device__ __align__(256) bf16 s_at_h[BB * NT * NT], s_at_l[BB * NT * NT];
__device__ __align__(256) bf16 s_y_h[BB * NT * CIN], s_y_l[BB * NT * CIN];
__device__ __align__(256) float s_wy[BB * CC * NT];

// ---------------- helpers ----------------
__device__ __forceinline__ uint32_t smem_u32(const void* p) {
    uint32_t a;
    asm("{ .reg .u64 t; cvta.to.shared.u64 t, %1; cvt.u32.u64 %0, t; }" : "=r"(a) : "l"(p));
    return a;
}
__device__ __forceinline__ void st_split2(bf16* hi, bf16* lo, float v0, float v1) {
    bf16 h0 = __float2bfloat16(v0), h1 = __float2bfloat16(v1);
    *(uint32_t*)hi = (uint32_t)__bfloat16_as_ushort(h0) |
                     ((uint32_t)__bfloat16_as_ushort(h1) << 16);
    bf16 l0 = __float2bfloat16(v0 - __bfloat162float(h0));
    bf16 l1 = __float2bfloat16(v1 - __bfloat162float(h1));
    *(uint32_t*)lo = (uint32_t)__bfloat16_as_ushort(l0) |
                     ((uint32_t)__bfloat16_as_ushort(l1) << 16);
}
__device__ __forceinline__ void st_split4(bf16* hi, bf16* lo, float v0, float v1, float v2, float v3) {
    st_split2(hi, lo, v0, v1);
    st_split2(hi + 2, lo + 2, v2, v3);
}

// ---------------- HMMA GEMM ----------------
// D[r,c] = sum_k (Ah+Al)[r,k] * (Bh+Bl)[c,k]   via HH + HL + LH
// CTA tile 128x128, K-chunk 64, 8 warps (2x4), warp tile 64x32, 3-stage cp.async.
#define NSTG 3
#define TILE_B 16384             // one 128x64 bf16 tile
#define STG_BYTES (4 * TILE_B)   // Ah/Al/Bh/Bl
#define SMEM_TOTAL (NSTG * STG_BYTES)

// swizzled byte offset of 16B vector (row, kv) in a 128x64 bf16 tile (128B rows)
__device__ __forceinline__ uint32_t sw_off(int row, int kv) {
    return (uint32_t)(row * 128 + ((kv ^ (row & 7)) << 4));
}

__device__ __forceinline__ void cpa_tile(uint32_t sdst, const bf16* __restrict__ g,
                                         int ld, int k0, int tid) {
#pragma unroll
    for (int i = 0; i < 4; i++) {
        int idx = tid + i * 256;       // 0..1023
        int row = idx >> 3;            // 0..127
        int kv  = idx & 7;             // 0..7
        uint32_t dst = sdst + sw_off(row, kv);
        const void* src = g + (long)row * ld + k0 + kv * 8;
        asm volatile("cp.async.cg.shared.global [%0], [%1], 16;" :: "r"(dst), "l"(src));
    }
}

__device__ __forceinline__ void ldmA(uint32_t* r, uint32_t base, int m0, int k16, int lane) {
    int m = m0 + (lane & 15);
    int kv = k16 * 2 + (lane >> 4);
    uint32_t addr = base + sw_off(m, kv);
    asm volatile("ldmatrix.sync.aligned.m8n8.x4.shared.b16 {%0,%1,%2,%3}, [%4];"
                 : "=r"(r[0]), "=r"(r[1]), "=r"(r[2]), "=r"(r[3]) : "r"(addr));
}
__device__ __forceinline__ void ldmB(uint32_t* r, uint32_t base, int n0, int k16, int lane) {
    int row = n0 + (lane & 7) + ((lane >> 4) << 3);
    int kv = k16 * 2 + ((lane >> 3) & 1);
    uint32_t addr = base + sw_off(row, kv);
    asm volatile("ldmatrix.sync.aligned.m8n8.x4.shared.b16 {%0,%1,%2,%3}, [%4];"
                 : "=r"(r[0]), "=r"(r[1]), "=r"(r[2]), "=r"(r[3]) : "r"(addr));
}
__device__ __forceinline__ void mmaOp(float* c, const uint32_t* a, const uint32_t* b) {
    asm volatile(
        "mma.sync.aligned.m16n8k16.row.col.f32.bf16.bf16.f32 "
        "{%0,%1,%2,%3},{%4,%5,%6,%7},{%8,%9},{%0,%1,%2,%3};"
        : "+f"(c[0]), "+f"(c[1]), "+f"(c[2]), "+f"(c[3])
        : "r"(a[0]), "r"(a[1]), "r"(a[2]), "r"(a[3]), "r"(b[0]), "r"(b[1]));
}

template <int OUT_SPLIT>
__global__ void __launch_bounds__(256, 1)
gemm_tc(const bf16* __restrict__ aH, const bf16* __restrict__ aL, long aS, int lda,
        const bf16* __restrict__ bH, const bf16* __restrict__ bL, long bS, int ldb,
        float* __restrict__ outF, bf16* __restrict__ oH, bf16* __restrict__ oL,
        long oS, int ldc, const float* __restrict__ rBias,
        const float* __restrict__ cBias, int K)
{
    extern __shared__ char smraw[];
    const uint32_t sb = smem_u32(smraw);

    const int tid = threadIdx.x, wid = tid >> 5, lane = tid & 31;
    const int bn = blockIdx.x * 128, bm = blockIdx.y * 128, bz = blockIdx.z;
    const int wm = (wid >> 2) * 64;
    const int wn = (wid & 3) * 32;

    const bf16* A0 = aH + (long)bz * aS + (long)bm * lda;
    const bf16* A1 = aL + (long)bz * aS + (long)bm * lda;
    const bf16* B0 = bH + (long)bz * bS + (long)bn * ldb;
    const bf16* B1 = bL + (long)bz * bS + (long)bn * ldb;
    const int nch = K >> 6;   // 64-wide chunks

    float acc[4][4][4];
#pragma unroll
    for (int i = 0; i < 4; i++)
#pragma unroll
        for (int j = 0; j < 4; j++)
#pragma unroll
            for (int e = 0; e < 4; e++) acc[i][j][e] = 0.f;

    // prologue: stages 0, 1
#pragma unroll
    for (int s = 0; s < NSTG - 1; s++) {
        uint32_t st = sb + s * STG_BYTES;
        int k0 = s << 6;
        cpa_tile(st,              A0, lda, k0, tid);
        cpa_tile(st + TILE_B,     A1, lda, k0, tid);
        cpa_tile(st + 2 * TILE_B, B0, ldb, k0, tid);
        cpa_tile(st + 3 * TILE_B, B1, ldb, k0, tid);
        asm volatile("cp.async.commit_group;");
    }

    for (int c = 0; c < nch; c++) {
        asm volatile("cp.async.wait_group 1;");
        __syncthreads();
        if (c + NSTG - 1 < nch) {
            uint32_t st = sb + ((c + NSTG - 1) % NSTG) * STG_BYTES;
            int k0 = (c + NSTG - 1) << 6;
            cpa_tile(st,              A0, lda, k0, tid);
            cpa_tile(st + TILE_B,     A1, lda, k0, tid);
            cpa_tile(st + 2 * TILE_B, B0, ldb, k0, tid);
            cpa_tile(st + 3 * TILE_B, B1, ldb, k0, tid);
        }
        asm volatile("cp.async.commit_group;");

        const uint32_t st = sb + (c % NSTG) * STG_BYTES;
#pragma unroll
        for (int k16 = 0; k16 < 4; k16++) {
            uint32_t fAh[4][4], fAl[4][4], fBh[2][4], fBl[2][4];
#pragma unroll
            for (int mt = 0; mt < 4; mt++) {
                ldmA(fAh[mt], st,          wm + mt * 16, k16, lane);
                ldmA(fAl[mt], st + TILE_B, wm + mt * 16, k16, lane);
            }
            ldmB(fBh[0], st + 2 * TILE_B, wn,      k16, lane);
            ldmB(fBh[1], st + 2 * TILE_B, wn + 16, k16, lane);
            ldmB(fBl[0], st + 3 * TILE_B, wn,      k16, lane);
            ldmB(fBl[1], st + 3 * TILE_B, wn + 16, k16, lane);
#pragma unroll
            for (int mt = 0; mt < 4; mt++) {
#pragma unroll
                for (int nt = 0; nt < 4; nt++) {
                    const uint32_t* bh = &fBh[nt >> 1][(nt & 1) * 2];
                    const uint32_t* bl = &fBl[nt >> 1][(nt & 1) * 2];
                    mmaOp(acc[mt][nt], fAh[mt], bh);
                    mmaOp(acc[mt][nt], fAh[mt], bl);
                    mmaOp(acc[mt][nt], fAl[mt], bh);
                }
            }
        }
        __syncthreads();
    }

    // epilogue
    const int rr = lane >> 2;
    const int cc2 = (lane & 3) * 2;
#pragma unroll
    for (int mt = 0; mt < 4; mt++) {
#pragma unroll
        for (int nt = 0; nt < 4; nt++) {
            int row0 = bm + wm + mt * 16 + rr;
            int col = bn + wn + nt * 8 + cc2;
            float cb0 = cBias ? cBias[col] : 0.f;
            float cb1 = cBias ? cBias[col + 1] : 0.f;
#pragma unroll
            for (int h = 0; h < 2; h++) {
                int row = row0 + h * 8;
                float rb = rBias ? rBias[row] : 0.f;
                float v0 = acc[mt][nt][h * 2 + 0] + rb + cb0;
                float v1 = acc[mt][nt][h * 2 + 1] + rb + cb1;
                long o = (long)bz * oS + (long)row * ldc + col;
                if (OUT_SPLIT == 0) {
                    *(float2*)(outF + o) = make_float2(v0, v1);
                } else {
                    st_split2(oH + o, oL + o, v0, v1);
                }
            }
        }
    }
}

// ---------------- elementwise kernels ----------------
// fused split of the 4 weight tensors (each 512*1024 elements)
__global__ void __launch_bounds__(256) split_w4(
    const float* __restrict__ w0, const float* __restrict__ w1,
    const float* __restrict__ w2, const float* __restrict__ w3,
    bf16* __restrict__ h0, bf16* __restrict__ l0,
    bf16* __restrict__ h1, bf16* __restrict__ l1,
    bf16* __restrict__ h2, bf16* __restrict__ l2,
    bf16* __restrict__ h3, bf16* __restrict__ l3)
{
    const int seg = blockIdx.x >> 11;            // 2048 blocks per segment
    const int i = (blockIdx.x & 2047) * 256 + threadIdx.x;
    const float* w = seg == 0 ? w0 : seg == 1 ? w1 : seg == 2 ? w2 : w3;
    bf16* hi = seg == 0 ? h0 : seg == 1 ? h1 : seg == 2 ? h2 : h3;
    bf16* lo = seg == 0 ? l0 : seg == 1 ? l1 : seg == 2 ? l2 : l3;
    float v = w[i];
    bf16 h = __float2bfloat16(v);
    hi[i] = h;
    lo[i] = __float2bfloat16(v - __bfloat162float(h));
}

__global__ void __launch_bounds__(256) xpose_split(const float* __restrict__ x,
                                                   bf16* __restrict__ hi, bf16* __restrict__ lo)
{
    __shared__ float t[32][33];
    const int b = blockIdx.z, n0 = blockIdx.x * 32, c0 = blockIdx.y * 32;
    const int tx = threadIdx.x & 31, ty = threadIdx.x >> 5;
#pragma unroll
    for (int i = 0; i < 4; i++) {
        int r = ty + i * 8;
        t[r][tx] = x[((long)b * CC + c0 + r) * NT + n0 + tx];
    }
    __syncthreads();
#pragma unroll
    for (int i = 0; i < 4; i++) {
        int r = ty + i * 8;
        float v = t[tx][r];
        long o = ((long)b * NT + n0 + r) * CC + c0 + tx;
        bf16 h = __float2bfloat16(v);
        hi[o] = h;
        lo[o] = __float2bfloat16(v - __bfloat162float(h));
    }
}

__global__ void __launch_bounds__(256) softmax_split(const float* __restrict__ f,
                                                     bf16* __restrict__ hi, bf16* __restrict__ lo)
{
    const float4* pv = (const float4*)(f + (size_t)blockIdx.x * NT);
    const int tid = threadIdx.x;
    float4 a = pv[tid], b = pv[tid + 256];
    float m = fmaxf(fmaxf(fmaxf(a.x, a.y), fmaxf(a.z, a.w)),
                    fmaxf(fmaxf(b.x, b.y), fmaxf(b.z, b.w)));
    __shared__ float red[8];
#pragma unroll
    for (int o = 16; o > 0; o >>= 1) m = fmaxf(m, __shfl_xor_sync(~0u, m, o));
    if ((tid & 31) == 0) red[tid >> 5] = m;
    __syncthreads();
    float mm = red[0];
#pragma unroll
    for (int i = 1; i < 8; i++) mm = fmaxf(mm, red[i]);
    __syncthreads();
    a.x = expf(a.x - mm); a.y = expf(a.y - mm); a.z = expf(a.z - mm); a.w = expf(a.w - mm);
    b.x = expf(b.x - mm); b.y = expf(b.y - mm); b.z = expf(b.z - mm); b.w = expf(b.w - mm);
    float s = (a.x + a.y) + (a.z + a.w) + (b.x + b.y) + (b.z + b.w);
#pragma unroll
    for (int o = 16; o > 0; o >>= 1) s += __shfl_xor_sync(~0u, s, o);
    if ((tid & 31) == 0) red[tid >> 5] = s;
    __syncthreads();
    float sum = 0.f;
#pragma unroll
    for (int i = 0; i < 8; i++) sum += red[i];
    float inv = 1.0f / sum;
    size_t off = (size_t)blockIdx.x * NT;
    st_split4(hi + off + tid * 4, lo + off + tid * 4,
              a.x * inv, a.y * inv, a.z * inv, a.w * inv);
    st_split4(hi + off + 1024 + tid * 4, lo + off + 1024 + tid * 4,
              b.x * inv, b.y * inv, b.z * inv, b.w * inv);
}

__global__ void __launch_bounds__(256)
bn_residual(const float* __restrict__ wy, const float* __restrict__ x,
            const float* __restrict__ gamma, const float* __restrict__ beta,
            float* __restrict__ out)
{
    const int c = blockIdx.x, tid = threadIdx.x;
    float vals[32], s = 0.f, ss = 0.f;
#pragma unroll
    for (int b = 0; b < BB; b++) {
        const float* p = wy + ((size_t)b * CC + c) * NT;
#pragma unroll
        for (int j = 0; j < 8; j++) {
            float v = p[tid + j * 256];
            vals[b * 8 + j] = v; s += v; ss += v * v;
        }
    }
    __shared__ float r1[8], r2[8];
#pragma unroll
    for (int o = 16; o > 0; o >>= 1) {
        s += __shfl_xor_sync(~0u, s, o);
        ss += __shfl_xor_sync(~0u, ss, o);
    }
    if ((tid & 31) == 0) { r1[tid >> 5] = s; r2[tid >> 5] = ss; }
    __syncthreads();
    s = 0.f; ss = 0.f;
#pragma unroll
    for (int i = 0; i < 8; i++) { s += r1[i]; ss += r2[i]; }
    const float cnt = (float)(BB * NT);
    float mean = s / cnt;
    float var = ss / cnt - mean * mean;
    float scale = rsqrtf(var + 1e-5f) * gamma[c];
    float shift = beta[c] - mean * scale;
#pragma unroll
    for (int b = 0; b < BB; b++) {
        size_t off = ((size_t)b * CC + c) * NT;
#pragma unroll
        for (int j = 0; j < 8; j++) {
            int n = tid + j * 256;
            out[off + n] = vals[b * 8 + j] * scale + shift + x[off + n];
        }
    }
}

// ---------------------------------------------------------------------------
extern "C" void kernel_launch(void* const* d_in, const int* in_sizes, int n_in,
                              void* d_out, int out_size)
{
    const float* x   = (const float*)d_in[0];
    const float* gw  = (const float*)d_in[1];
    const float* gb  = (const float*)d_in[2];
    const float* tw  = (const float*)d_in[3];
    const float* tb  = (const float*)d_in[4];
    const float* pw  = (const float*)d_in[5];
    const float* pb  = (const float*)d_in[6];
    const float* ww  = (const float*)d_in[7];
    const float* wb  = (const float*)d_in[8];
    const float* bg  = (const float*)d_in[9];
    const float* bbt = (const float*)d_in[10];
    float* out = (float*)d_out;

    bf16 *xTh, *xTl, *wgh, *wgl, *wth, *wtl, *wph, *wpl, *wwh, *wwl;
    bf16 *thh, *thl, *phh, *phl, *gsh, *gsl, *ath, *atl, *yh, *yl;
    float *ff, *wy;
    cudaGetSymbolAddress((void**)&xTh, s_xT_h); cudaGetSymbolAddress((void**)&xTl, s_xT_l);
    cudaGetSymbolAddress((void**)&wgh, s_wg_h); cudaGetSymbolAddress((void**)&wgl, s_wg_l);
    cudaGetSymbolAddress((void**)&wth, s_wt_h); cudaGetSymbolAddress((void**)&wtl, s_wt_l);
    cudaGetSymbolAddress((void**)&wph, s_wp_h); cudaGetSymbolAddress((void**)&wpl, s_wp_l);
    cudaGetSymbolAddress((void**)&wwh, s_ww_h); cudaGetSymbolAddress((void**)&wwl, s_ww_l);
    cudaGetSymbolAddress((void**)&thh, s_th_h); cudaGetSymbolAddress((void**)&thl, s_th_l);
    cudaGetSymbolAddress((void**)&phh, s_ph_h); cudaGetSymbolAddress((void**)&phl, s_ph_l);
    cudaGetSymbolAddress((void**)&gsh, s_gs_h); cudaGetSymbolAddress((void**)&gsl, s_gs_l);
    cudaGetSymbolAddress((void**)&ath, s_at_h); cudaGetSymbolAddress((void**)&atl, s_at_l);
    cudaGetSymbolAddress((void**)&yh,  s_y_h);  cudaGetSymbolAddress((void**)&yl,  s_y_l);
    cudaGetSymbolAddress((void**)&ff,  s_f);    cudaGetSymbolAddress((void**)&wy,  s_wy);

    cudaFuncSetAttribute(gemm_tc<0>, cudaFuncAttributeMaxDynamicSharedMemorySize, SMEM_TOTAL);
    cudaFuncSetAttribute(gemm_tc<1>, cudaFuncAttributeMaxDynamicSharedMemorySize, SMEM_TOTAL);

    split_w4<<<4 * 2048, 256>>>(gw, tw, pw, ww,
                                wgh, wgl, wth, wtl, wph, wpl, wwh, wwl);
    xpose_split<<<dim3(NT / 32, CC / 32, BB), 256>>>(x, xTh, xTl);

    const long sXT = (long)NT * CC, sPR = (long)NT * CIN;
    const long sGS = (long)CIN * NT, sAT = (long)NT * NT, sWY = (long)CC * NT;

    // theta[b,n,o] (rows=NT, cols=CIN, K=CC)
    gemm_tc<1><<<dim3(CIN / 128, NT / 128, BB), 256, SMEM_TOTAL>>>(
        xTh, xTl, sXT, CC, wth, wtl, 0, CC, nullptr, thh, thl, sPR, CIN, nullptr, tb, CC);
    // phi[b,n,o]
    gemm_tc<1><<<dim3(CIN / 128, NT / 128, BB), 256, SMEM_TOTAL>>>(
        xTh, xTl, sXT, CC, wph, wpl, 0, CC, nullptr, phh, phl, sPR, CIN, nullptr, pb, CC);
    // g_s[b,o,m] (rows=CIN, cols=NT, K=CC)
    gemm_tc<1><<<dim3(NT / 128, CIN / 128, BB), 256, SMEM_TOTAL>>>(
        wgh, wgl, 0, CC, xTh, xTl, sXT, CC, nullptr, gsh, gsl, sGS, NT, gb, nullptr, CC);
    // f[b,n,m] (rows=NT, cols=NT, K=CIN)
    gemm_tc<0><<<dim3(NT / 128, NT / 128, BB), 256, SMEM_TOTAL>>>(
        thh, thl, sPR, CIN, phh, phl, sPR, CIN, ff, nullptr, nullptr, sAT, NT, nullptr, nullptr, CIN);
    // softmax -> split attn
    softmax_split<<<BB * NT, 256>>>(ff, ath, atl);
    // y[b,n,o] (rows=NT, cols=CIN, K=NT)
    gemm_tc<1><<<dim3(CIN / 128, NT / 128, BB), 256, SMEM_TOTAL>>>(
        ath, atl, sAT, NT, gsh, gsl, sGS, NT, nullptr, yh, yl, sPR, CIN, nullptr, nullptr, NT);
    // w_y[b,c,n] (rows=CC, cols=NT, K=CIN)
    gemm_tc<0><<<dim3(NT / 128, CC / 128, BB), 256, SMEM_TOTAL>>>(
        wwh, wwl, 0, CIN, yh, yl, sPR, CIN, wy, nullptr, nullptr, sWY, NT, wb, nullptr, CIN);
    // BN + residual
    bn_residual<<<CC, 256>>>(wy, x, bg, bbt, out);
}